// round 1
// baseline (speedup 1.0000x reference)
#include <cuda_runtime.h>

#define NTHR 128
#define HALO 2048
// SMEM: 12288 floats = 49152 bytes (exactly the 48KB static limit)

__device__ __forceinline__ float2 ffma2(float2 a, float2 b, float2 c) {
    float2 d;
    asm("fma.rn.f32x2 %0, %1, %2, %3;"
        : "=l"(reinterpret_cast<unsigned long long&>(d))
        : "l"(reinterpret_cast<unsigned long long&>(a)),
          "l"(reinterpret_cast<unsigned long long&>(b)),
          "l"(reinterpret_cast<unsigned long long&>(c)));
    return d;
}

// conv (8 k-chains, f32x2 over a position pair) + per-position epilogue
__device__ __forceinline__ void conv_pair(const float2* __restrict__ wp,
                                          const float2 xv[9],
                                          int posBase, int nPos,
                                          float cmax[8], int cnt[8])
{
    float2 z[8];
#pragma unroll
    for (int k = 0; k < 8; k++) z[k] = make_float2(0.f, 0.f);
#pragma unroll
    for (int r = 0; r < 9; r++) {
        float2 x2 = xv[r];
#pragma unroll
        for (int k = 0; k < 8; k++) z[k] = ffma2(wp[k * 9 + r], x2, z[k]);
    }
#pragma unroll
    for (int s = 0; s < 2; s++) {
        float z0 = s ? z[0].y : z[0].x;
        float m = z0, n = z0;
        int   mi = 0, ni = 0;
#pragma unroll
        for (int k = 1; k < 8; k++) {
            float zk = s ? z[k].y : z[k].x;
            bool gt = zk > m;  m = gt ? zk : m;  mi = gt ? k : mi;
            bool lt = zk < n;  n = lt ? zk : n;  ni = lt ? k : ni;
        }
        if (posBase + s < nPos) {
#pragma unroll
            for (int i = 0; i < 8; i++) {
                cmax[i] += (mi == i) ? m : 0.f;
                cnt[i]  += (ni == i) ? 1 : 0;
            }
        }
    }
}

__global__ __launch_bounds__(NTHR, 2)
void hydra_kernel(const float* __restrict__ X, const float* __restrict__ W,
                  const int* __restrict__ I, float* __restrict__ out)
{
    __shared__ float A[12288];

    const int bid = blockIdx.x;
    const int g  = bid & 31;
    const int j  = (bid >> 5) & 1;
    const int di = (bid >> 6) % 10;
    const int b  = bid / 640;
    const int d  = 1 << di;
    const int tid = threadIdx.x;

    // ---- zero smem (interior + halos) ----
    float4* A4 = (float4*)A;
#pragma unroll 4
    for (int i = tid; i < 3072; i += NTHR) A4[i] = make_float4(0.f, 0.f, 0.f, 0.f);

    // ---- per-block metadata ----
    const int* Ib = I + ((di * 2 + j) * 32 + g) * 6;
    const int ic0 = Ib[0], ic1 = Ib[1], ic2 = Ib[2], ic3 = Ib[3], ic4 = Ib[4], ic5 = Ib[5];

    const float* Wb = W + ((di * 2 + j) * 256 + g * 8) * 9;
    float2 wp[72];
#pragma unroll
    for (int i = 0; i < 72; i++) { float w = __ldg(Wb + i); wp[i] = make_float2(w, w); }

    __syncthreads();

    // ---- build channel-sum into interior [HALO, HALO+8192) ----
    const float4* X4 = (const float4*)X;
    const int rb = b * 12 * 2048;
#pragma unroll 2
    for (int t = tid; t < 2048; t += NTHR) {
        float4 s = X4[rb + ic0 * 2048 + t];
        float4 v;
        v = X4[rb + ic1 * 2048 + t]; s.x += v.x; s.y += v.y; s.z += v.z; s.w += v.w;
        v = X4[rb + ic2 * 2048 + t]; s.x += v.x; s.y += v.y; s.z += v.z; s.w += v.w;
        v = X4[rb + ic3 * 2048 + t]; s.x += v.x; s.y += v.y; s.z += v.z; s.w += v.w;
        v = X4[rb + ic4 * 2048 + t]; s.x += v.x; s.y += v.y; s.z += v.z; s.w += v.w;
        v = X4[rb + ic5 * 2048 + t]; s.x += v.x; s.y += v.y; s.z += v.z; s.w += v.w;
        A4[512 + t] = s;
    }
    __syncthreads();

    // ---- j==1: in-place first difference (chunked, WAR-safe) ----
    int nPos = 8192;
    if (j == 1) {
        nPos = 8191;
#pragma unroll 1
        for (int base = 0; base < 8192; base += NTHR) {
            const int idx = base + tid;
            const bool ok = idx < 8191;
            float v = 0.f;
            if (ok) v = A[HALO + idx + 1] - A[HALO + idx];
            __syncthreads();
            if (ok) A[HALO + idx] = v;
        }
        if (tid == 0) A[HALO + 8191] = 0.f;
        __syncthreads();
    }

    // ---- conv + histogram main loop ----
    float cmax[8];
    int   cnt[8];
#pragma unroll
    for (int k = 0; k < 8; k++) { cmax[k] = 0.f; cnt[k] = 0; }

    const float2* A2 = (const float2*)A;

    if (d == 1) {
#pragma unroll 1
        for (int p = tid; p < 4096; p += NTHR) {
            float2 v0 = A2[1022 + p], v1 = A2[1023 + p], v2 = A2[1024 + p],
                   v3 = A2[1025 + p], v4 = A2[1026 + p];
            float2 xv[9];
            xv[0] = v0; xv[2] = v1; xv[4] = v2; xv[6] = v3; xv[8] = v4;
            xv[1] = make_float2(v0.y, v1.x);
            xv[3] = make_float2(v1.y, v2.x);
            xv[5] = make_float2(v2.y, v3.x);
            xv[7] = make_float2(v3.y, v4.x);
            conv_pair(wp, xv, 2 * p, nPos, cmax, cnt);
        }
    } else {
        const int hd = d >> 1;
#pragma unroll 1
        for (int p = tid; p < 4096; p += NTHR) {
            float2 xv[9];
#pragma unroll
            for (int r = 0; r < 9; r++) xv[r] = A2[1024 + p + (r - 4) * hd];
            conv_pair(wp, xv, 2 * p, nPos, cmax, cnt);
        }
    }

    // ---- block reduction (smem A reused as scratch) ----
    __syncthreads();
    if (tid < 16) A[tid] = 0.f;
    __syncthreads();

    const int lane = tid & 31;
#pragma unroll
    for (int k = 0; k < 8; k++) {
        float v = cmax[k];
        int   c = cnt[k];
#pragma unroll
        for (int off = 16; off; off >>= 1) {
            v += __shfl_down_sync(0xffffffffu, v, off);
            c += __shfl_down_sync(0xffffffffu, c, off);
        }
        if (lane == 0) {
            atomicAdd(&A[k], v);
            atomicAdd((int*)A + 8 + k, c);
        }
    }
    __syncthreads();

    // ---- write outputs: rows (di*2+j)*2*32+g (cmax) and +32 (cmin) ----
    const int rowBase = ((di * 2 + j) * 2) * 32 + g;
    if (tid < 8) {
        float v = A[tid];
        out[(b * 1280 + rowBase) * 8 + tid] = v > 0.f ? v : 0.f;
    } else if (tid < 16) {
        const int k = tid - 8;
        const int c = ((const int*)A)[8 + k];
        out[(b * 1280 + rowBase + 32) * 8 + k] = (float)c;
    }
}

extern "C" void kernel_launch(void* const* d_in, const int* in_sizes, int n_in,
                              void* d_out, int out_size)
{
    const float* X = (const float*)d_in[0];
    const float* W = (const float*)d_in[1];
    const int*   I = (const int*)d_in[2];
    float*       O = (float*)d_out;
    hydra_kernel<<<20480, NTHR>>>(X, W, I, O);
}